// round 8
// baseline (speedup 1.0000x reference)
#include <cuda_runtime.h>
#include <cstdint>
#include <cstddef>

#define NEDGES 500000
#define NNODES 200000

constexpr int MROWS   = 500096;            // mult of 128
constexpr int TILES64 = MROWS / 64;        // 7814
constexpr int TILESH  = MROWS / 128;       // 3907

// ---------------- device scratch ----------------
__device__ float g_X1[(size_t)MROWS * 512];
__device__ float g_X2[(size_t)MROWS * 512];
__device__ float g_W0t[8 * 512 * 32];         // [kc][n][k] tf32
__device__ float g_Wht[2 * 16 * 512 * 32];    // [l][kc][n][k] tf32
__device__ float g_WHt[32 * 512];             // [n][k] tf32
__device__ float g_sc[3 * 512];
__device__ float g_sh[3 * 512];
__device__ float g_hb[32];

// ---------------- helpers ----------------
__device__ __forceinline__ float tf32r(float x) {
    unsigned u;
    asm("cvt.rna.tf32.f32 %0, %1;" : "=r"(u) : "f"(x));
    return __uint_as_float(u);
}
__device__ __forceinline__ float actf(float v) {
    v = v > 0.f ? v : expm1f(v);
    return tf32r(v);
}
__device__ __forceinline__ void cp16(void* s, const void* g) {
    unsigned ss = (unsigned)__cvta_generic_to_shared(s);
    asm volatile("cp.async.cg.shared.global [%0], [%1], 16;\n" :: "r"(ss), "l"(g));
}
__device__ __forceinline__ void cp16s(uint32_t s, const void* g) {
    asm volatile("cp.async.cg.shared.global [%0], [%1], 16;\n" :: "r"(s), "l"(g));
}
__device__ __forceinline__ void cp_commit() { asm volatile("cp.async.commit_group;\n"); }
template<int N> __device__ __forceinline__ void cp_wait() {
    asm volatile("cp.async.wait_group %0;\n" :: "n"(N) : "memory");
}
__device__ __forceinline__ void mma8(float* c,
                                     unsigned a0, unsigned a1, unsigned a2, unsigned a3,
                                     float fb0, float fb1) {
    unsigned b0 = __float_as_uint(fb0), b1 = __float_as_uint(fb1);
    asm volatile(
        "mma.sync.aligned.m16n8k8.row.col.f32.tf32.tf32.f32 "
        "{%0,%1,%2,%3},{%4,%5,%6,%7},{%8,%9},{%0,%1,%2,%3};"
        : "+f"(c[0]), "+f"(c[1]), "+f"(c[2]), "+f"(c[3])
        : "r"(a0), "r"(a1), "r"(a2), "r"(a3), "r"(b0), "r"(b1));
}
__device__ __forceinline__ int bswz_of(int n) { return ((n & 1) << 4) | ((n & 2) << 1); }

// ---------------- prep ----------------
__global__ void prep_kernel(
    const float* __restrict__ W0,  const float* __restrict__ b0,
    const float* __restrict__ Wh,  const float* __restrict__ bh,
    const float* __restrict__ gm,  const float* __restrict__ bt,
    const float* __restrict__ mn,  const float* __restrict__ vr,
    const float* __restrict__ Wpi, const float* __restrict__ bpi,
    const float* __restrict__ Wsg, const float* __restrict__ bsg,
    const float* __restrict__ Wmu, const float* __restrict__ bmu)
{
    int st = gridDim.x * blockDim.x;
    int t0 = blockIdx.x * blockDim.x + threadIdx.x;
    for (int o = t0; o < 8 * 512 * 32; o += st) {
        int kc = o >> 14, n = (o >> 5) & 511, kk = o & 31;
        g_W0t[o] = tf32r(W0[(size_t)(kc * 32 + kk) * 512 + n]);
    }
    for (int o = t0; o < 2 * 16 * 512 * 32; o += st) {
        int l = o >> 18;
        int kc = (o >> 14) & 15, n = (o >> 5) & 511, kk = o & 31;
        g_Wht[o] = tf32r(Wh[(size_t)l * 262144 + (size_t)(kc * 32 + kk) * 512 + n]);
    }
    for (int o = t0; o < 32 * 512; o += st) {
        int n = o >> 9, k = o & 511;
        float v = (n < 10) ? Wpi[k * 10 + n]
                : (n < 20) ? Wsg[k * 10 + (n - 10)]
                : (n < 30) ? Wmu[k * 10 + (n - 20)] : 0.f;
        g_WHt[o] = tf32r(v);
    }
    for (int i = t0; i < 3 * 512; i += st) {
        int l = i >> 9, c = i & 511;
        float s = gm[i] * rsqrtf(vr[i] + 1e-5f);
        float bb = (l == 0) ? b0[c] : bh[(l - 1) * 512 + c];
        g_sc[i] = s;
        g_sh[i] = (bb - mn[i]) * s + bt[i];
    }
    for (int i = t0; i < 32; i += st)
        g_hb[i] = (i < 10) ? bpi[i] : (i < 20) ? bsg[i - 10] : (i < 30) ? bmu[i - 20] : 0.f;
}

// ---------------- main fused GEMM ----------------
// CTA tile M=64 x N=128, 128 threads (4 warps, warp tile 32x64), 4 CTAs/SM.
// K chunk 32, 2-stage ring, 2 barriers/chunk. grid (4 n-passes, TILES64).
// smem floats: As[2][64][32] | Bs[2][128][32] @4096 | sIdx[128] @12288
constexpr int SMEM_MAIN_F = 12288 + 128;
constexpr int SMEM_MAIN_B = SMEM_MAIN_F * 4;   // 49,664 B (x4 CTAs = 198,656)

template<int KDIM, bool GATHER>
__global__ void __launch_bounds__(128, 4)
gemm_kernel(const float* __restrict__ Ag,
            const int*   __restrict__ edges,
            const float* __restrict__ W,      // chunk-major [KDIM/32][512][32] tf32
            const float* __restrict__ sc,
            const float* __restrict__ sh,
            float* __restrict__ outp)
{
    extern __shared__ float sm[];
    float* As   = sm;                 // 2 * 2048
    float* Bs   = sm + 4096;          // 2 * 4096
    int*   sIdx = (int*)(sm + 12288);

    const int tid  = threadIdx.x;
    const int tile = blockIdx.y;
    const int n0   = blockIdx.x * 128;
    constexpr int NC = KDIM / 32;

    if (GATHER) {
        if (tid < 64) {
            int e = tile * 64 + tid;
            bool v = e < NEDGES;
            sIdx[tid]      = v ? edges[NEDGES + e] : 0;   // k 0..127   = h[edge[1]]
            sIdx[64 + tid] = v ? edges[e]          : 0;   // k 128..255 = h[edge[0]]
        }
        __syncthreads();
    }

    // ---- hoisted cp.async descriptors (o = tid + it*128: seg invariant, r += 16/it) ----
    const int seg = tid & 7;
    const int r0  = tid >> 3;            // 0..15
    const uint32_t sAb = (uint32_t)__cvta_generic_to_shared(As);
    const uint32_t sBb = (uint32_t)__cvta_generic_to_shared(Bs);
    const uint32_t dA0 = sAb + (uint32_t)(r0 * 32 + ((seg * 4) ^ ((r0 & 1) << 4))) * 4;
    const uint32_t dB0 = sBb + (uint32_t)(r0 * 32 + ((seg * 4) ^ bswz_of(r0))) * 4;
    const float* srcA0 = GATHER ? Ag : (Ag + (size_t)(tile * 64 + r0) * KDIM + seg * 4);
    const float* srcB0 = W + (size_t)(n0 + r0) * 32 + seg * 4;

    auto prefetch = [&](int kc) {
        const int stg = kc & 1;
        const uint32_t soA = (uint32_t)stg * 8192;    // bytes
        const uint32_t soB = (uint32_t)stg * 16384;
        if (GATHER) {
            const int half = (kc < 4) ? 0 : 64;
            const int kof  = (kc & 3) * 32 + seg * 4;
            #pragma unroll
            for (int it = 0; it < 4; it++) {
                int node = sIdx[half + r0 + it * 16];
                cp16s(dA0 + soA + it * 2048, Ag + (size_t)node * 128 + kof);
            }
        } else {
            const float* s = srcA0 + kc * 32;
            #pragma unroll
            for (int it = 0; it < 4; it++)
                cp16s(dA0 + soA + it * 2048, s + (size_t)it * 16 * KDIM);
        }
        const float* sb = srcB0 + (size_t)kc * 16384;
        #pragma unroll
        for (int it = 0; it < 8; it++)
            cp16s(dB0 + soB + it * 2048, sb + it * 512);
        cp_commit();
    };

    // ---- warp fragment constants (warp tile 32x64) ----
    const int wid = tid >> 5, lane = tid & 31;
    const int wm = wid >> 1, wn = wid & 1;        // 2x2 warp grid
    const int g = lane >> 2, tig = lane & 3;
    const int koffA0 = (4 * tig) ^ ((g & 1) << 4);
    const int koffA1 = koffA0 ^ 16;
    const int koffB0 = (4 * tig) ^ bswz_of(g);
    const int koffB1 = koffB0 ^ 16;
    const int aoff = (wm * 32 + g) * 32;
    const int boff = (wn * 64 + g) * 32;

    float c[2][8][4];
    #pragma unroll
    for (int i = 0; i < 2; i++)
        #pragma unroll
        for (int j = 0; j < 8; j++)
            #pragma unroll
            for (int q = 0; q < 4; q++) c[i][j][q] = 0.f;

    prefetch(0);
    prefetch(1);

    #pragma unroll 1
    for (int kc = 0; kc < NC; kc++) {
        if (kc + 1 < NC) cp_wait<1>(); else cp_wait<0>();
        __syncthreads();                          // stage kc data visible

        const int stg = kc & 1;
        const float* Ab = As + stg * 2048 + aoff;
        const float* Bb = Bs + stg * 4096 + boff;

        #pragma unroll
        for (int h = 0; h < 2; h++) {
            const int kA = h ? koffA1 : koffA0;
            const int kB = h ? koffB1 : koffB0;
            float4 alo[2], ahi[2];
            #pragma unroll
            for (int mf = 0; mf < 2; mf++) {
                alo[mf] = *(const float4*)(Ab + mf * 512 + kA);
                ahi[mf] = *(const float4*)(Ab + mf * 512 + 256 + kA);
            }
            #pragma unroll
            for (int half = 0; half < 2; half++) {   // nf groups of 4 (limits live regs)
                float4 bb[4];
                #pragma unroll
                for (int j = 0; j < 4; j++)
                    bb[j] = *(const float4*)(Bb + (half * 4 + j) * 256 + kB);
                #pragma unroll
                for (int s = 0; s < 2; s++)
                    #pragma unroll
                    for (int mf = 0; mf < 2; mf++) {
                        unsigned a0 = __float_as_uint(s ? alo[mf].z : alo[mf].x);
                        unsigned a2 = __float_as_uint(s ? alo[mf].w : alo[mf].y);
                        unsigned a1 = __float_as_uint(s ? ahi[mf].z : ahi[mf].x);
                        unsigned a3 = __float_as_uint(s ? ahi[mf].w : ahi[mf].y);
                        #pragma unroll
                        for (int j = 0; j < 4; j++)
                            mma8(c[mf][half * 4 + j], a0, a1, a2, a3,
                                 s ? bb[j].z : bb[j].x, s ? bb[j].w : bb[j].y);
                    }
            }
        }

        __syncthreads();                          // all reads of stage kc done
        if (kc + 2 < NC) prefetch(kc + 2);        // safe to overwrite stage kc&1
    }

    // epilogue
    size_t rowbase = (size_t)tile * 64;
    #pragma unroll
    for (int nf = 0; nf < 8; nf++) {
        int col = n0 + wn * 64 + nf * 8 + 2 * tig;
        float s0 = __ldg(sc + col), s1 = __ldg(sc + col + 1);
        float t0 = __ldg(sh + col), t1 = __ldg(sh + col + 1);
        #pragma unroll
        for (int mf = 0; mf < 2; mf++) {
            int r = wm * 32 + mf * 16 + g;
            float2 v01, v23;
            v01.x = actf(s0 * c[mf][nf][0] + t0);
            v01.y = actf(s1 * c[mf][nf][1] + t1);
            v23.x = actf(s0 * c[mf][nf][2] + t0);
            v23.y = actf(s1 * c[mf][nf][3] + t1);
            *(float2*)(outp + (rowbase + r) * 512 + col)     = v01;
            *(float2*)(outp + (rowbase + r + 8) * 512 + col) = v23;
        }
    }
}

// ---------------- head kernel (validated) ----------------
__global__ void __launch_bounds__(256, 1)
head_kernel(const float* __restrict__ A,
            const float* __restrict__ Wt,    // [32 n][512 k] tf32
            const float* __restrict__ dist,
            float* __restrict__ out)
{
    extern __shared__ float hsm[];
    float* Bp = hsm;                 // 16384
    float* As = hsm + 16384;         // 8192
    float* sZ = hsm + 16384 + 8192;  // 128*33

    const int tid  = threadIdx.x;
    const int tile = blockIdx.x;

    #pragma unroll
    for (int it = 0; it < 16; it++) {
        int o = tid + it * 256;
        int n = o >> 7, ks = o & 127;
        cp16(Bp + n * 512 + ((ks * 4) ^ bswz_of(n)), Wt + (size_t)n * 512 + ks * 4);
    }

    auto loadA = [&](int kc, int buf) {
        #pragma unroll
        for (int it = 0; it < 4; it++) {
            int o = tid + it * 256;
            int r = o >> 3, sg = o & 7;
            cp16(As + buf * 4096 + r * 32 + ((sg * 4) ^ ((r & 1) << 4)),
                 A + (size_t)(tile * 128 + r) * 512 + kc * 32 + sg * 4);
        }
    };

    const int wid = tid >> 5, lane = tid & 31;
    const int g = lane >> 2, tig = lane & 3;
    const int aswz = (g & 1) << 4;
    const int bswz = bswz_of(g);
    int koffA[2], koffB[2];
    koffA[0] = (4 * tig) ^ aswz;  koffA[1] = (16 + 4 * tig) ^ aswz;
    koffB[0] = (4 * tig) ^ bswz;  koffB[1] = (16 + 4 * tig) ^ bswz;
    const float* pA = As + (wid * 16 + g) * 32;
    const float* pB = Bp + g * 512;

    float c[4][4];
    #pragma unroll
    for (int i = 0; i < 4; i++)
        #pragma unroll
        for (int q = 0; q < 4; q++) c[i][q] = 0.f;

    loadA(0, 0); cp_commit();

    #pragma unroll 1
    for (int kc = 0; kc < 16; kc++) {
        int buf = kc & 1;
        __syncthreads();
        if (kc + 1 < 16) { loadA(kc + 1, buf ^ 1); cp_commit(); cp_wait<1>(); }
        else             { cp_wait<0>(); }
        __syncthreads();

        const float* Ab = pA + buf * 4096;
        const float* Bb = pB + kc * 32;
        #pragma unroll
        for (int h = 0; h < 2; h++) {
            float4 bb[4];
            #pragma unroll
            for (int nf = 0; nf < 4; nf++)
                bb[nf] = *(const float4*)(Bb + nf * 4096 + koffB[h]);
            float4 lo = *(const float4*)(Ab + koffA[h]);
            float4 hi = *(const float4*)(Ab + 256 + koffA[h]);
            #pragma unroll
            for (int s = 0; s < 2; s++) {
                unsigned a0 = __float_as_uint(s ? lo.z : lo.x);
                unsigned a2 = __float_as_uint(s ? lo.w : lo.y);
                unsigned a1 = __float_as_uint(s ? hi.z : hi.x);
                unsigned a3 = __float_as_uint(s ? hi.w : hi.y);
                #pragma unroll
                for (int nf = 0; nf < 4; nf++)
                    mma8(c[nf], a0, a1, a2, a3,
                         s ? bb[nf].z : bb[nf].x, s ? bb[nf].w : bb[nf].y);
            }
        }
    }

    {
        int r0 = wid * 16 + g;
        #pragma unroll
        for (int nf = 0; nf < 4; nf++) {
            int co = nf * 8 + 2 * tig;
            sZ[r0 * 33 + co]           = c[nf][0];
            sZ[r0 * 33 + co + 1]       = c[nf][1];
            sZ[(r0 + 8) * 33 + co]     = c[nf][2];
            sZ[(r0 + 8) * 33 + co + 1] = c[nf][3];
        }
    }
    __syncthreads();

    if (tid < 128) {
        int e = tile * 128 + tid;
        if (e < NEDGES) {
            float z[30];
            #pragma unroll
            for (int k = 0; k < 30; k++) z[k] = sZ[tid * 33 + k] + g_hb[k];
            float m = z[0];
            #pragma unroll
            for (int k = 1; k < 10; k++) m = fmaxf(m, z[k]);
            float ez[10], sum = 0.f;
            #pragma unroll
            for (int k = 0; k < 10; k++) { ez[k] = expf(z[k] - m); sum += ez[k]; }
            float inv = 1.f / sum;
            #pragma unroll
            for (int k = 0; k < 10; k++) out[(size_t)e * 10 + k] = ez[k] * inv;
            #pragma unroll
            for (int k = 0; k < 10; k++) {
                float v = z[10 + k];
                v = v > 0.f ? v : expm1f(v);
                out[5000000u + (size_t)e * 10 + k] = v + 1.1f;
            }
            #pragma unroll
            for (int k = 0; k < 10; k++) {
                float v = z[20 + k];
                v = v > 0.f ? v : expm1f(v);
                out[10000000u + (size_t)e * 10 + k] = v + 1.0f;
            }
            out[15000000u + e] = __ldg(dist + e);
        }
    }
}

// ---------------- launch ----------------
extern "C" void kernel_launch(void* const* d_in, const int* in_sizes, int n_in,
                              void* d_out, int out_size) {
    (void)in_sizes; (void)n_in; (void)out_size;
    const float* h    = (const float*)d_in[0];
    const int*   edges= (const int*)  d_in[1];
    const float* dist = (const float*)d_in[2];
    const float* W0   = (const float*)d_in[3];
    const float* b0   = (const float*)d_in[4];
    const float* Wh   = (const float*)d_in[5];
    const float* bh   = (const float*)d_in[6];
    const float* gm   = (const float*)d_in[7];
    const float* bt   = (const float*)d_in[8];
    const float* mn   = (const float*)d_in[9];
    const float* vr   = (const float*)d_in[10];
    const float* Wpi  = (const float*)d_in[11];
    const float* bpi  = (const float*)d_in[12];
    const float* Wsg  = (const float*)d_in[13];
    const float* bsg  = (const float*)d_in[14];
    const float* Wmu  = (const float*)d_in[15];
    const float* bmu  = (const float*)d_in[16];
    float* out = (float*)d_out;

    const int SMEM_HEAD = (16384 + 8192 + 128 * 33) * 4;   // 115,200 B
    cudaFuncSetAttribute(gemm_kernel<256, true>,  cudaFuncAttributeMaxDynamicSharedMemorySize, SMEM_MAIN_B);
    cudaFuncSetAttribute(gemm_kernel<512, false>, cudaFuncAttributeMaxDynamicSharedMemorySize, SMEM_MAIN_B);
    cudaFuncSetAttribute(head_kernel,             cudaFuncAttributeMaxDynamicSharedMemorySize, SMEM_HEAD);

    float *X1, *X2, *W0t, *Wht, *WHt, *sc, *sh;
    cudaGetSymbolAddress((void**)&X1,  g_X1);
    cudaGetSymbolAddress((void**)&X2,  g_X2);
    cudaGetSymbolAddress((void**)&W0t, g_W0t);
    cudaGetSymbolAddress((void**)&Wht, g_Wht);
    cudaGetSymbolAddress((void**)&WHt, g_WHt);
    cudaGetSymbolAddress((void**)&sc,  g_sc);
    cudaGetSymbolAddress((void**)&sh,  g_sh);

    prep_kernel<<<256, 256>>>(W0, b0, Wh, bh, gm, bt, mn, vr,
                              Wpi, bpi, Wsg, bsg, Wmu, bmu);

    dim3 grid(4, TILES64);
    gemm_kernel<256, true ><<<grid, 128, SMEM_MAIN_B>>>(h,  edges,   W0t,                 sc,        sh,        X1);
    gemm_kernel<512, false><<<grid, 128, SMEM_MAIN_B>>>(X1, nullptr, Wht,                 sc + 512,  sh + 512,  X2);
    gemm_kernel<512, false><<<grid, 128, SMEM_MAIN_B>>>(X2, nullptr, Wht + 16 * 512 * 32, sc + 1024, sh + 1024, X1);
    head_kernel<<<TILESH, 256, SMEM_HEAD>>>(X1, WHt, dist, out);
}

// round 10
// speedup vs baseline: 1.4378x; 1.4378x over previous
#include <cuda_runtime.h>
#include <cuda_fp16.h>
#include <cstdint>
#include <cstddef>

#define NEDGES 500000
#define NNODES 200000

constexpr int MROWS   = 500096;            // mult of 128
constexpr int TILES64 = MROWS / 64;        // 7814
constexpr int TILESH  = MROWS / 128;       // 3907

// ---------------- device scratch ----------------
__device__ __half g_hp[(size_t)NNODES * 128];       // h fp16, k-permuted per 32-chunk
__device__ __half g_X1[(size_t)MROWS * 512];        // activations fp16, k-permuted
__device__ __half g_X2[(size_t)MROWS * 512];
__device__ __half g_W0h[8 * 512 * 32];              // [kc][n][kp] fp16
__device__ __half g_Whh[2 * 16 * 512 * 32];         // [l][kc][n][kp] fp16
__device__ __half g_WHh[16 * 32 * 32];              // head W [kc][n][kp] fp16
__device__ float  g_sc[3 * 512];
__device__ float  g_sh[3 * 512];
__device__ float  g_hb[32];

// k-permutation within a 32-k chunk: lane tig gets its 8 fragment halves contiguous.
// p = tig*8 + s*4 + i  <->  k = 16*s + 2*tig + (i&1) + 8*(i>>1)
__host__ __device__ __forceinline__ int kperm(int k) {
    return ((k & 7) >> 1) * 8 + ((k >> 4) & 1) * 4 + ((k >> 3) & 1) * 2 + (k & 1);
}

// ---------------- helpers ----------------
__device__ __forceinline__ void cp16s(uint32_t s, const void* g) {
    asm volatile("cp.async.cg.shared.global [%0], [%1], 16;\n" :: "r"(s), "l"(g));
}
__device__ __forceinline__ void cp16(void* s, const void* g) {
    unsigned ss = (unsigned)__cvta_generic_to_shared(s);
    asm volatile("cp.async.cg.shared.global [%0], [%1], 16;\n" :: "r"(ss), "l"(g));
}
__device__ __forceinline__ void cp_commit() { asm volatile("cp.async.commit_group;\n"); }
template<int N> __device__ __forceinline__ void cp_wait() {
    asm volatile("cp.async.wait_group %0;\n" :: "n"(N) : "memory");
}
__device__ __forceinline__ void mma16(float* c,
                                      unsigned a0, unsigned a1, unsigned a2, unsigned a3,
                                      unsigned b0, unsigned b1) {
    asm volatile(
        "mma.sync.aligned.m16n8k16.row.col.f32.f16.f16.f32 "
        "{%0,%1,%2,%3},{%4,%5,%6,%7},{%8,%9},{%0,%1,%2,%3};"
        : "+f"(c[0]), "+f"(c[1]), "+f"(c[2]), "+f"(c[3])
        : "r"(a0), "r"(a1), "r"(a2), "r"(a3), "r"(b0), "r"(b1));
}
__device__ __forceinline__ float eluf(float v) { return v > 0.f ? v : expm1f(v); }

// ---------------- prep: convert everything to permuted fp16, fold BN ----------------
__global__ void prep_kernel(
    const float* __restrict__ h,
    const float* __restrict__ W0,  const float* __restrict__ b0,
    const float* __restrict__ Wh,  const float* __restrict__ bh,
    const float* __restrict__ gm,  const float* __restrict__ bt,
    const float* __restrict__ mn,  const float* __restrict__ vr,
    const float* __restrict__ Wpi, const float* __restrict__ bpi,
    const float* __restrict__ Wsg, const float* __restrict__ bsg,
    const float* __restrict__ Wmu, const float* __restrict__ bmu)
{
    int st = gridDim.x * blockDim.x;
    int t0 = blockIdx.x * blockDim.x + threadIdx.x;
    // node features -> fp16, permuted within each 32-chunk
    for (int o = t0; o < NNODES * 128; o += st) {
        int node = o >> 7, kk = o & 127;
        int ch = kk >> 5, k = kk & 31;
        g_hp[(size_t)node * 128 + ch * 32 + kperm(k)] = __float2half(h[o]);
    }
    // layer-1 weights [kc][n][kp]
    for (int o = t0; o < 8 * 512 * 32; o += st) {
        int kc = o >> 14, n = (o >> 5) & 511, k = o & 31;
        g_W0h[(size_t)kc * 16384 + n * 32 + kperm(k)] =
            __float2half(W0[(size_t)(kc * 32 + k) * 512 + n]);
    }
    // hidden weights
    for (int o = t0; o < 2 * 16 * 512 * 32; o += st) {
        int l = o >> 18;
        int kc = (o >> 14) & 15, n = (o >> 5) & 511, k = o & 31;
        g_Whh[(size_t)l * 262144 + (size_t)kc * 16384 + n * 32 + kperm(k)] =
            __float2half(Wh[(size_t)l * 262144 + (size_t)(kc * 32 + k) * 512 + n]);
    }
    // head weights [kc][n 32][kp]
    for (int o = t0; o < 16 * 32 * 32; o += st) {
        int kc = o >> 10, n = (o >> 5) & 31, k = o & 31;
        int kk = kc * 32 + k;
        float v = (n < 10) ? Wpi[kk * 10 + n]
                : (n < 20) ? Wsg[kk * 10 + (n - 10)]
                : (n < 30) ? Wmu[kk * 10 + (n - 20)] : 0.f;
        g_WHh[kc * 1024 + n * 32 + kperm(k)] = __float2half(v);
    }
    for (int i = t0; i < 3 * 512; i += st) {
        int l = i >> 9, c = i & 511;
        float s = gm[i] * rsqrtf(vr[i] + 1e-5f);
        float bb = (l == 0) ? b0[c] : bh[(l - 1) * 512 + c];
        g_sc[i] = s;
        g_sh[i] = (bb - mn[i]) * s + bt[i];
    }
    for (int i = t0; i < 32; i += st)
        g_hb[i] = (i < 10) ? bpi[i] : (i < 20) ? bsg[i - 10] : (i < 30) ? bmu[i - 20] : 0.f;
}

// ---------------- main fused GEMM (fp16) ----------------
// CTA tile M=64 x N=128, 128 threads (4 warps, warp 32x64), 4 CTAs/SM.
// K chunk 32, 3-stage ring, 1 barrier/chunk. grid (4 n-passes, TILES64).
// smem bytes: As[3][64 rows][64B] =12288 | Bs[3][128][64B] =24576 @12288 | sIdx @36864
constexpr int SMEM_MAIN_B = 12288 + 24576 + 512;   // 37376 (x4 CTAs = 149,504)

template<int KDIM, bool GATHER>
__global__ void __launch_bounds__(128, 4)
gemm_kernel(const __half* __restrict__ Ag,    // GATHER: g_hp; else X fp16 permuted
            const int*    __restrict__ edges,
            const __half* __restrict__ W,     // [KDIM/32][512][32] fp16 permuted
            const float*  __restrict__ sc,
            const float*  __restrict__ sh,
            __half* __restrict__ outp)        // [MROWS][512] fp16 permuted
{
    extern __shared__ char sm[];
    char* As = sm;                     // 3 * 4096 B
    char* Bs = sm + 12288;             // 3 * 8192 B
    int*  sIdx = (int*)(sm + 36864);

    const int tid  = threadIdx.x;
    const int tile = blockIdx.y;
    const int n0   = blockIdx.x * 128;
    constexpr int NC = KDIM / 32;

    if (GATHER) {
        if (tid < 64) {
            int e = tile * 64 + tid;
            bool v = e < NEDGES;
            sIdx[tid]      = v ? edges[NEDGES + e] : 0;   // k 0..127   = h[edge[1]]
            sIdx[64 + tid] = v ? edges[e]          : 0;   // k 128..255 = h[edge[0]]
        }
        __syncthreads();
    }

    // ---- hoisted cp.async descriptors: 16B per thread-slot, 64B rows ----
    const int seg = tid & 3;               // 16B segment in 64B row
    const int r0  = tid >> 2;              // 0..31
    const uint32_t sAb = (uint32_t)__cvta_generic_to_shared(As);
    const uint32_t sBb = (uint32_t)__cvta_generic_to_shared(Bs);
    const uint32_t dA0 = sAb + (uint32_t)(r0 * 64 + seg * 16);
    const uint32_t dB0 = sBb + (uint32_t)(r0 * 64 + seg * 16);
    const char* AgB = (const char*)Ag;
    const char* WB  = (const char*)W;
    const char* srcA0 = GATHER ? nullptr
                               : AgB + (size_t)(tile * 64 + r0) * (KDIM * 2) + seg * 16;
    const char* srcB0 = WB + (size_t)(n0 + r0) * 64 + seg * 16;

    auto prefetch = [&](int kc) {
        const int stg = kc % 3;
        const uint32_t soA = (uint32_t)stg * 4096;
        const uint32_t soB = (uint32_t)stg * 8192;
        if (GATHER) {
            const int half = (kc < 4) ? 0 : 64;
            const int kof  = (kc & 3) * 64 + seg * 16;
            #pragma unroll
            for (int it = 0; it < 2; it++) {          // 64 rows / 32
                int node = sIdx[half + r0 + it * 32];
                cp16s(dA0 + soA + it * 2048, AgB + (size_t)node * 256 + kof);
            }
        } else {
            const char* s = srcA0 + kc * 64;
            #pragma unroll
            for (int it = 0; it < 2; it++)
                cp16s(dA0 + soA + it * 2048, s + (size_t)it * 32 * (KDIM * 2));
        }
        const char* sb = srcB0 + (size_t)kc * 32768;
        #pragma unroll
        for (int it = 0; it < 4; it++)                // 128 n-rows / 32
            cp16s(dB0 + soB + it * 2048, sb + (size_t)it * 2048);
        cp_commit();
    };

    // ---- warp fragment constants (warp tile 32x64) ----
    const int wid = tid >> 5, lane = tid & 31;
    const int wm = wid >> 1, wn = wid & 1;            // 2x2 warp grid
    const int g = lane >> 2, tig = lane & 3;
    const int aoff = (wm * 32 + g) * 64 + tig * 16;   // bytes
    const int boff = (wn * 64 + g) * 64 + tig * 16;

    float c[2][8][4];
    #pragma unroll
    for (int i = 0; i < 2; i++)
        #pragma unroll
        for (int j = 0; j < 8; j++)
            #pragma unroll
            for (int q = 0; q < 4; q++) c[i][j][q] = 0.f;

    prefetch(0);
    prefetch(1);

    #pragma unroll 1
    for (int kc = 0; kc < NC; kc++) {
        if (kc + 1 < NC) cp_wait<1>(); else cp_wait<0>();
        __syncthreads();                 // stage kc visible; stage (kc+2)%3 drained at kc-1
        if (kc + 2 < NC) prefetch(kc + 2);

        const int stg = kc % 3;
        const char* Ab = As + stg * 4096 + aoff;
        const char* Bb = Bs + stg * 8192 + boff;

        // A fragments: uint4 = {a0(s0), a2(s0), a0(s1), a2(s1)} etc.
        uint4 Ar[4];
        Ar[0] = *(const uint4*)(Ab);            // mf0 row g    -> (a0,a2)
        Ar[1] = *(const uint4*)(Ab + 512);      // mf0 row g+8  -> (a1,a3)
        Ar[2] = *(const uint4*)(Ab + 1024);     // mf1 row g
        Ar[3] = *(const uint4*)(Ab + 1536);     // mf1 row g+8
        #pragma unroll
        for (int half = 0; half < 2; half++) {
            uint4 Bv[4];
            #pragma unroll
            for (int j = 0; j < 4; j++)
                Bv[j] = *(const uint4*)(Bb + (half * 4 + j) * 512);
            #pragma unroll
            for (int s = 0; s < 2; s++)
                #pragma unroll
                for (int mf = 0; mf < 2; mf++) {
                    unsigned a0 = s ? Ar[2 * mf].z     : Ar[2 * mf].x;
                    unsigned a2 = s ? Ar[2 * mf].w     : Ar[2 * mf].y;
                    unsigned a1 = s ? Ar[2 * mf + 1].z : Ar[2 * mf + 1].x;
                    unsigned a3 = s ? Ar[2 * mf + 1].w : Ar[2 * mf + 1].y;
                    #pragma unroll
                    for (int j = 0; j < 4; j++)
                        mma16(c[mf][half * 4 + j], a0, a1, a2, a3,
                              s ? Bv[j].z : Bv[j].x, s ? Bv[j].w : Bv[j].y);
                }
        }
    }

    // epilogue: y = s*acc + t, ELU, fp16, permuted store
    size_t rowbase = (size_t)tile * 64;
    #pragma unroll
    for (int nf = 0; nf < 8; nf++) {
        int col = n0 + wn * 64 + nf * 8 + 2 * tig;
        float s0 = __ldg(sc + col), s1 = __ldg(sc + col + 1);
        float t0 = __ldg(sh + col), t1 = __ldg(sh + col + 1);
        int pcol = (col & ~31) + kperm(col & 31);       // permuted column
        #pragma unroll
        for (int mf = 0; mf < 2; mf++) {
            int r = wm * 32 + mf * 16 + g;
            __half2 v01 = __floats2half2_rn(eluf(s0 * c[mf][nf][0] + t0),
                                            eluf(s1 * c[mf][nf][1] + t1));
            __half2 v23 = __floats2half2_rn(eluf(s0 * c[mf][nf][2] + t0),
                                            eluf(s1 * c[mf][nf][3] + t1));
            *(__half2*)(outp + (rowbase + r) * 512 + pcol)     = v01;
            *(__half2*)(outp + (rowbase + r + 8) * 512 + pcol) = v23;
        }
    }
}

// ---------------- head kernel (fp16): [128][512] @ [512][32] + softmax/ELU + dist ----------------
// smem: Bp[16 kc][32 n][64B] =32768 | As[2][128][64B] =16384 @32768 | sZ[128*33 f32] @49152
constexpr int SMEM_HEAD_B = 32768 + 16384 + 128 * 33 * 4;   // 66,048 B

__global__ void __launch_bounds__(256, 1)
head_kernel(const __half* __restrict__ A,     // X fp16 permuted
            const __half* __restrict__ Wt,    // [16][32][32] fp16 permuted
            const float*  __restrict__ dist,
            float* __restrict__ out)
{
    extern __shared__ char hsm[];
    char*  Bp = hsm;
    char*  As = hsm + 32768;
    float* sZ = (float*)(hsm + 49152);

    const int tid  = threadIdx.x;
    const int tile = blockIdx.x;
    const char* AB = (const char*)A;

    // resident head weights: layout identical global<->smem, linear copy (32KB)
    #pragma unroll
    for (int it = 0; it < 8; it++) {
        int o = tid + it * 256;
        cp16(Bp + o * 16, (const char*)Wt + o * 16);
    }

    auto loadA = [&](int kc, int buf) {
        #pragma unroll
        for (int it = 0; it < 2; it++) {
            int o = tid + it * 256;
            int r = o >> 2, sg = o & 3;
            cp16(As + buf * 8192 + r * 64 + sg * 16,
                 AB + (size_t)(tile * 128 + r) * 1024 + kc * 64 + sg * 16);
        }
    };

    const int wid = tid >> 5, lane = tid & 31;
    const int g = lane >> 2, tig = lane & 3;
    const int aoff = (wid * 16 + g) * 64 + tig * 16;
    const int boff = g * 64 + tig * 16;

    float c[4][4];
    #pragma unroll
    for (int i = 0; i < 4; i++)
        #pragma unroll
        for (int q = 0; q < 4; q++) c[i][q] = 0.f;

    loadA(0, 0); cp_commit();

    #pragma unroll 1
    for (int kc = 0; kc < 16; kc++) {
        int buf = kc & 1;
        __syncthreads();
        if (kc + 1 < 16) { loadA(kc + 1, buf ^ 1); cp_commit(); cp_wait<1>(); }
        else             { cp_wait<0>(); }
        __syncthreads();

        const char* Ab = As + buf * 8192 + aoff;
        const char* Bb = Bp + kc * 2048 + boff;
        uint4 A0 = *(const uint4*)(Ab);
        uint4 A1 = *(const uint4*)(Ab + 512);
        uint4 Bv[4];
        #pragma unroll
        for (int j = 0; j < 4; j++)
            Bv[j] = *(const uint4*)(Bb + j * 512);
        #pragma unroll
        for (int s = 0; s < 2; s++) {
            unsigned a0 = s ? A0.z : A0.x;
            unsigned a2 = s ? A0.w : A0.y;
            unsigned a1 = s ? A1.z : A1.x;
            unsigned a3 = s ? A1.w : A1.y;
            #pragma unroll
            for (int j = 0; j < 4; j++)
                mma16(c[j], a0, a1, a2, a3,
                      s ? Bv[j].z : Bv[j].x, s ? Bv[j].w : Bv[j].y);
        }
    }

    {
        int r0 = wid * 16 + g;
        #pragma unroll
        for (int nf = 0; nf < 4; nf++) {
            int co = nf * 8 + 2 * tig;
            sZ[r0 * 33 + co]           = c[nf][0];
            sZ[r0 * 33 + co + 1]       = c[nf][1];
            sZ[(r0 + 8) * 33 + co]     = c[nf][2];
            sZ[(r0 + 8) * 33 + co + 1] = c[nf][3];
        }
    }
    __syncthreads();

    if (tid < 128) {
        int e = tile * 128 + tid;
        if (e < NEDGES) {
            float z[30];
            #pragma unroll
            for (int k = 0; k < 30; k++) z[k] = sZ[tid * 33 + k] + g_hb[k];
            float m = z[0];
            #pragma unroll
            for (int k = 1; k < 10; k++) m = fmaxf(m, z[k]);
            float ez[10], sum = 0.f;
            #pragma unroll
            for (int k = 0; k < 10; k++) { ez[k] = expf(z[k] - m); sum += ez[k]; }
            float inv = 1.f / sum;
            #pragma unroll
            for (int k = 0; k < 10; k++) out[(size_t)e * 10 + k] = ez[k] * inv;
            #pragma unroll
            for (int k = 0; k < 10; k++)
                out[5000000u + (size_t)e * 10 + k] = eluf(z[10 + k]) + 1.1f;
            #pragma unroll
            for (int k = 0; k < 10; k++)
                out[10000000u + (size_t)e * 10 + k] = eluf(z[20 + k]) + 1.0f;
            out[15000000u + e] = __ldg(dist + e);
        }
    }
}

// ---------------- launch ----------------
extern "C" void kernel_launch(void* const* d_in, const int* in_sizes, int n_in,
                              void* d_out, int out_size) {
    (void)in_sizes; (void)n_in; (void)out_size;
    const float* h    = (const float*)d_in[0];
    const int*   edges= (const int*)  d_in[1];
    const float* dist = (const float*)d_in[2];
    const float* W0   = (const float*)d_in[3];
    const float* b0   = (const float*)d_in[4];
    const float* Wh   = (const float*)d_in[5];
    const float* bh   = (const float*)d_in[6];
    const float* gm   = (const float*)d_in[7];
    const float* bt   = (const float*)d_in[8];
    const float* mn   = (const float*)d_in[9];
    const float* vr   = (const float*)d_in[10];
    const float* Wpi  = (const float*)d_in[11];
    const float* bpi  = (const float*)d_in[12];
    const float* Wsg  = (const float*)d_in[13];
    const float* bsg  = (const float*)d_in[14];
    const float* Wmu  = (const float*)d_in[15];
    const float* bmu  = (const float*)d_in[16];
    float* out = (float*)d_out;

    cudaFuncSetAttribute(gemm_kernel<256, true>,  cudaFuncAttributeMaxDynamicSharedMemorySize, SMEM_MAIN_B);
    cudaFuncSetAttribute(gemm_kernel<512, false>, cudaFuncAttributeMaxDynamicSharedMemorySize, SMEM_MAIN_B);
    cudaFuncSetAttribute(head_kernel,             cudaFuncAttributeMaxDynamicSharedMemorySize, SMEM_HEAD_B);

    __half *hp, *X1, *X2, *W0h, *Whh, *WHh;
    float *sc, *sh;
    cudaGetSymbolAddress((void**)&hp,  g_hp);
    cudaGetSymbolAddress((void**)&X1,  g_X1);
    cudaGetSymbolAddress((void**)&X2,  g_X2);
    cudaGetSymbolAddress((void**)&W0h, g_W0h);
    cudaGetSymbolAddress((void**)&Whh, g_Whh);
    cudaGetSymbolAddress((void**)&WHh, g_WHh);
    cudaGetSymbolAddress((void**)&sc,  g_sc);
    cudaGetSymbolAddress((void**)&sh,  g_sh);

    prep_kernel<<<512, 256>>>(h, W0, b0, Wh, bh, gm, bt, mn, vr,
                              Wpi, bpi, Wsg, bsg, Wmu, bmu);

    dim3 grid(4, TILES64);
    gemm_kernel<256, true ><<<grid, 128, SMEM_MAIN_B>>>(hp, edges,   W0h,                 sc,        sh,        X1);
    gemm_kernel<512, false><<<grid, 128, SMEM_MAIN_B>>>(X1, nullptr, Whh,                 sc + 512,  sh + 512,  X2);
    gemm_kernel<512, false><<<grid, 128, SMEM_MAIN_B>>>(X2, nullptr, Whh + 16 * 512 * 32, sc + 1024, sh + 1024, X1);
    head_kernel<<<TILESH, 256, SMEM_HEAD_B>>>(X1, WHh, dist, out);
}